// round 10
// baseline (speedup 1.0000x reference)
#include <cuda_runtime.h>

#define B_ 16
#define S_ 512
#define D_ 256
#define H_ 8
#define DH_ 32

// Scratch (static device arrays — no allocations allowed)
__device__ float g_q[B_*S_*D_];
__device__ float g_k[B_*S_*D_];
__device__ float g_v[B_*S_*D_];
__device__ float g_tr[(size_t)B_*S_*S_];   // TR[b,q,j] = c2*time_attn + c3*rel_attn (head-independent)

__device__ __forceinline__ float ex2f_(float x){
    float y; asm("ex2.approx.ftz.f32 %0, %1;" : "=f"(y) : "f"(x)); return y;
}
__device__ __forceinline__ float fexp_(float x){ return ex2f_(x * 1.4426950408889634f); }

// ---------------------------------------------------------------------------
// Kernel 1: projections  P = X @ W^T + b  (M=8192, N=256, K=256)
// 128x128 block tile, 8x8 per-thread microtile, double-buffered smem,
// register prefetch, one __syncthreads per 16-wide k-slab.
// ---------------------------------------------------------------------------
__global__ void __launch_bounds__(256, 2) proj_kernel(
    const float* __restrict__ Xq, const float* __restrict__ Xk, const float* __restrict__ Xv,
    const float* __restrict__ Wq, const float* __restrict__ Wk, const float* __restrict__ Wv,
    const float* __restrict__ bq, const float* __restrict__ bk, const float* __restrict__ bv)
{
    __shared__ float As[2][16][132];   // [buf][k][m]
    __shared__ float Bs[2][16][132];   // [buf][k][n]

    int z = blockIdx.z;
    const float* X    = (z==0) ? Xq : ((z==1) ? Xk : Xv);
    const float* W    = (z==0) ? Wq : ((z==1) ? Wk : Wv);
    const float* bias = (z==0) ? bq : ((z==1) ? bk : bv);
    float*       O    = (z==0) ? g_q : ((z==1) ? g_k : g_v);

    int m0 = blockIdx.x * 128, n0 = blockIdx.y * 128;
    int tid = threadIdx.x;
    int tm = tid >> 4, tn = tid & 15;        // 16x16 threads; 8 rows x 8 cols each
    int lr = tid >> 1, lk = (tid & 1) * 8;   // loader: row lr, k-offset lk (8 floats)

    const float* Arow = &X[(size_t)(m0 + lr) * 256 + lk];
    const float* Brow = &W[(size_t)(n0 + lr) * 256 + lk];

    float acc[8][8];
    #pragma unroll
    for (int i = 0; i < 8; i++)
        #pragma unroll
        for (int j = 0; j < 8; j++) acc[i][j] = 0.f;

    float4 na0, na1, nb0, nb1;
    na0 = *(const float4*)(Arow);     na1 = *(const float4*)(Arow + 4);
    nb0 = *(const float4*)(Brow);     nb1 = *(const float4*)(Brow + 4);

    #define PROJ_STORE(bf) {                                                     \
        As[bf][lk+0][lr]=na0.x; As[bf][lk+1][lr]=na0.y;                          \
        As[bf][lk+2][lr]=na0.z; As[bf][lk+3][lr]=na0.w;                          \
        As[bf][lk+4][lr]=na1.x; As[bf][lk+5][lr]=na1.y;                          \
        As[bf][lk+6][lr]=na1.z; As[bf][lk+7][lr]=na1.w;                          \
        Bs[bf][lk+0][lr]=nb0.x; Bs[bf][lk+1][lr]=nb0.y;                          \
        Bs[bf][lk+2][lr]=nb0.z; Bs[bf][lk+3][lr]=nb0.w;                          \
        Bs[bf][lk+4][lr]=nb1.x; Bs[bf][lk+5][lr]=nb1.y;                          \
        Bs[bf][lk+6][lr]=nb1.z; Bs[bf][lk+7][lr]=nb1.w; }

    PROJ_STORE(0);
    __syncthreads();

    int buf = 0;
    for (int step = 0; step < 16; step++) {
        if (step < 15) {
            int k0 = (step + 1) * 16;
            na0 = *(const float4*)(Arow + k0);  na1 = *(const float4*)(Arow + k0 + 4);
            nb0 = *(const float4*)(Brow + k0);  nb1 = *(const float4*)(Brow + k0 + 4);
        }
        #pragma unroll
        for (int kk = 0; kk < 16; kk++) {
            float4 a0 = *(const float4*)&As[buf][kk][tm*8];
            float4 a1 = *(const float4*)&As[buf][kk][tm*8 + 4];
            float4 b0 = *(const float4*)&Bs[buf][kk][tn*8];
            float4 b1 = *(const float4*)&Bs[buf][kk][tn*8 + 4];
            float ar[8] = {a0.x,a0.y,a0.z,a0.w,a1.x,a1.y,a1.z,a1.w};
            float br[8] = {b0.x,b0.y,b0.z,b0.w,b1.x,b1.y,b1.z,b1.w};
            #pragma unroll
            for (int i = 0; i < 8; i++)
                #pragma unroll
                for (int j = 0; j < 8; j++)
                    acc[i][j] += ar[i]*br[j];
        }
        if (step < 15) {
            int nx = buf ^ 1;
            PROJ_STORE(nx);
            __syncthreads();
            buf = nx;
        }
    }

    float4 bl = *(const float4*)&bias[n0 + tn*8];
    float4 bh = *(const float4*)&bias[n0 + tn*8 + 4];
    #pragma unroll
    for (int i = 0; i < 8; i++) {
        float* orow = &O[(size_t)(m0 + tm*8 + i) * 256 + n0 + tn*8];
        float4 o0, o1;
        o0.x = acc[i][0] + bl.x; o0.y = acc[i][1] + bl.y;
        o0.z = acc[i][2] + bl.z; o0.w = acc[i][3] + bl.w;
        o1.x = acc[i][4] + bh.x; o1.y = acc[i][5] + bh.y;
        o1.z = acc[i][6] + bh.z; o1.w = acc[i][7] + bh.w;
        *(float4*)orow = o0;
        *(float4*)(orow + 4) = o1;
    }
    #undef PROJ_STORE
}

// ---------------------------------------------------------------------------
// Kernel 2: TR precompute (head-independent blend of time/rel softmaxes)
// ---------------------------------------------------------------------------
__global__ void __launch_bounds__(256) tr_kernel(
    const float* __restrict__ rel, const float* __restrict__ ts,
    const float* __restrict__ l1p, const float* __restrict__ l2p)
{
    int w = blockIdx.x * 8 + (threadIdx.x >> 5);  // row (b*S + q)
    int lane = threadIdx.x & 31;
    int q = w & (S_ - 1);
    const float* relrow = rel + (size_t)w * S_;
    const float* tsrow  = ts  + (size_t)w * S_;

    float l1 = *l1p, l2 = *l2p;
    float c2 = (1.f - l1) * l2, c3 = l1;

    float tv[16], rv[16];
    float tsum = 0.f, rsum = 0.f;
    #pragma unroll
    for (int u = 0; u < 4; u++) {
        int j0 = lane * 4 + u * 128;
        float4 r4 = *(const float4*)&relrow[j0];
        float4 t4 = *(const float4*)&tsrow[j0];
        float rc[4] = {r4.x, r4.y, r4.z, r4.w};
        float tc[4] = {t4.x, t4.y, t4.z, t4.w};
        #pragma unroll
        for (int jj = 0; jj < 4; jj++) {
            int j = j0 + jj;
            float tnum = (j <= q) ? fexp_(fexp_(-fabsf(tc[jj]))) : 0.f;
            float rnum = (j > q && rc[jj] != 0.f) ? fexp_(rc[jj]) : 0.f;
            tv[4*u + jj] = tnum;  rv[4*u + jj] = rnum;
            tsum += tnum;  rsum += rnum;
        }
    }
    #pragma unroll
    for (int off = 16; off; off >>= 1) {
        tsum += __shfl_xor_sync(0xffffffffu, tsum, off);
        rsum += __shfl_xor_sync(0xffffffffu, rsum, off);
    }
    float tmul = c2 / tsum;
    float rmul = (rsum > 0.f) ? (c3 / rsum) : 0.f;
    float radd = (rsum > 0.f) ? 0.f : (c3 * (1.f / 512.f));

    float* trrow = g_tr + (size_t)w * S_;
    #pragma unroll
    for (int u = 0; u < 4; u++) {
        int j0 = lane * 4 + u * 128;
        float4 o;
        o.x = tv[4*u+0]*tmul + rv[4*u+0]*rmul + radd;
        o.y = tv[4*u+1]*tmul + rv[4*u+1]*rmul + radd;
        o.z = tv[4*u+2]*tmul + rv[4*u+2]*rmul + radd;
        o.w = tv[4*u+3]*tmul + rv[4*u+3]*rmul + radd;
        *(float4*)&trrow[j0] = o;
    }
}

// ---------------------------------------------------------------------------
// Kernel 3: fused attention. CTA = (q-tile of 32 rows, head, batch).
// Double-buffered K/V tiles with register prefetch; one barrier per chunk.
// ---------------------------------------------------------------------------
#define SC_FLOATS   (32*512)
#define QST_FLOATS  (32*32)
#define KTT_FLOATS  (32*132)
#define ATTN_SMEM   ((SC_FLOATS + QST_FLOATS + 2*KTT_FLOATS) * 4)

__global__ void __launch_bounds__(256, 2) attn_kernel(
    const float* __restrict__ l1p, const float* __restrict__ l2p,
    float* __restrict__ out, float* __restrict__ prob)
{
    extern __shared__ float sm_[];
    float* sc  = sm_;                          // [32][512]
    float* QsT = sm_ + SC_FLOATS;              // [d=32][q=32]
    float* KB  = QsT + QST_FLOATS;             // two [32][132] buffers (K, then reused for V)

    int tid = threadIdx.x;
    int lane = tid & 31;
    int qg = tid >> 5;       // warp id: rows 4*qg .. 4*qg+3
    int kg = lane;
    int qt = blockIdx.x, h = blockIdx.y, b = blockIdx.z;
    int q0 = qt * 32;

    // loader mapping for K/V chunk (128 rows x 32 d): 4 float4 per thread
    int jr_[4], d0_[4];
    #pragma unroll
    for (int t = 0; t < 4; t++) { int id = tid + t*256; jr_[t] = id >> 3; d0_[t] = (id & 7) * 4; }

    float4 pr[4];
    #define LOAD_CHUNK(SRC, c) {                                                       \
        int jc = (c) * 128;                                                            \
        _Pragma("unroll")                                                              \
        for (int t = 0; t < 4; t++)                                                    \
            pr[t] = *(const float4*)&SRC[(size_t)(b*S_ + jc + jr_[t]) * D_ + h*DH_ + d0_[t]]; }
    #define STORE_CHUNK(bf) {                                                          \
        float* T = KB + (bf) * KTT_FLOATS;                                             \
        _Pragma("unroll")                                                              \
        for (int t = 0; t < 4; t++) {                                                  \
            T[(d0_[t]+0)*132 + jr_[t]] = pr[t].x;  T[(d0_[t]+1)*132 + jr_[t]] = pr[t].y; \
            T[(d0_[t]+2)*132 + jr_[t]] = pr[t].z;  T[(d0_[t]+3)*132 + jr_[t]] = pr[t].w; } }

    // Q tile load (transposed into d-major) + K chunk 0 prefetch
    {
        int qr = tid >> 3, d0 = (tid & 7) * 4;
        float4 qv = *(const float4*)&g_q[(size_t)(b*S_ + q0 + qr) * D_ + h*DH_ + d0];
        LOAD_CHUNK(g_k, 0);
        QsT[(d0+0)*32 + qr] = qv.x; QsT[(d0+1)*32 + qr] = qv.y;
        QsT[(d0+2)*32 + qr] = qv.z; QsT[(d0+3)*32 + qr] = qv.w;
        STORE_CHUNK(0);
    }
    __syncthreads();

    const float SCALE = 0.25504570f;   // log2(e) / sqrt(32): softmax in base-2 domain
    float lmax[4] = {-1e30f, -1e30f, -1e30f, -1e30f};

    // ----- Phase A: scores -----
    for (int c = 0; c < 4; c++) {
        if (c < 3) LOAD_CHUNK(g_k, c+1);
        const float* KtT = KB + (c & 1) * KTT_FLOATS;

        float acc[4][4];
        #pragma unroll
        for (int i = 0; i < 4; i++)
            #pragma unroll
            for (int j = 0; j < 4; j++) acc[i][j] = 0.f;

        #pragma unroll
        for (int d = 0; d < 32; d++) {
            float4 qv = *(const float4*)&QsT[d*32 + qg*4];     // warp-broadcast
            float4 kv = *(const float4*)&KtT[d*132 + kg*4];
            acc[0][0] += qv.x*kv.x; acc[0][1] += qv.x*kv.y; acc[0][2] += qv.x*kv.z; acc[0][3] += qv.x*kv.w;
            acc[1][0] += qv.y*kv.x; acc[1][1] += qv.y*kv.y; acc[1][2] += qv.y*kv.z; acc[1][3] += qv.y*kv.w;
            acc[2][0] += qv.z*kv.x; acc[2][1] += qv.z*kv.y; acc[2][2] += qv.z*kv.z; acc[2][3] += qv.z*kv.w;
            acc[3][0] += qv.w*kv.x; acc[3][1] += qv.w*kv.y; acc[3][2] += qv.w*kv.z; acc[3][3] += qv.w*kv.w;
        }
        int j0 = c*128 + kg*4;
        #pragma unroll
        for (int i = 0; i < 4; i++) {
            int qglob = q0 + qg*4 + i;
            float4 v;
            v.x = (j0+0 > qglob) ? -1e9f : acc[i][0]*SCALE;
            v.y = (j0+1 > qglob) ? -1e9f : acc[i][1]*SCALE;
            v.z = (j0+2 > qglob) ? -1e9f : acc[i][2]*SCALE;
            v.w = (j0+3 > qglob) ? -1e9f : acc[i][3]*SCALE;
            lmax[i] = fmaxf(lmax[i], fmaxf(fmaxf(v.x, v.y), fmaxf(v.z, v.w)));
            *(float4*)&sc[(qg*4 + i)*512 + j0] = v;
        }
        if (c < 3) {
            STORE_CHUNK((c+1) & 1);
            __syncthreads();
        }
    }
    #pragma unroll
    for (int off = 16; off; off >>= 1) {
        #pragma unroll
        for (int i = 0; i < 4; i++)
            lmax[i] = fmaxf(lmax[i], __shfl_xor_sync(0xffffffffu, lmax[i], off));
    }
    __syncwarp();

    // Prefetch V chunk 0 (latency hidden under phase B)
    LOAD_CHUNK(g_v, 0);

    // ----- Phase B: softmax + blend + prob write (warp-local rows, no barrier) -----
    float l1 = *l1p, l2 = *l2p;
    float c1 = (1.f - l1) * (1.f - l2);

    #pragma unroll
    for (int i = 0; i < 4; i++) {
        int r = qg*4 + i;
        int qglob = q0 + r;
        float* row = &sc[r * 512];
        float e[16];
        float s = 0.f;
        float mx = lmax[i];
        #pragma unroll
        for (int u = 0; u < 4; u++) {
            float4 v = *(const float4*)&row[lane*4 + u*128];
            e[4*u+0] = ex2f_(v.x - mx);
            e[4*u+1] = ex2f_(v.y - mx);
            e[4*u+2] = ex2f_(v.z - mx);
            e[4*u+3] = ex2f_(v.w - mx);
            s += (e[4*u+0] + e[4*u+1]) + (e[4*u+2] + e[4*u+3]);
        }
        #pragma unroll
        for (int off = 16; off; off >>= 1) s += __shfl_xor_sync(0xffffffffu, s, off);
        float sA = c1 / s;

        const float* trrow = &g_tr[(size_t)(b*S_ + qglob) * S_];
        float* probrow = &prob[(size_t)((b*H_ + h)*S_ + qglob) * S_];
        #pragma unroll
        for (int u = 0; u < 4; u++) {
            int j0 = lane*4 + u*128;
            float4 t4 = *(const float4*)&trrow[j0];
            float4 p;
            p.x = e[4*u+0]*sA + t4.x;
            p.y = e[4*u+1]*sA + t4.y;
            p.z = e[4*u+2]*sA + t4.z;
            p.w = e[4*u+3]*sA + t4.w;
            *(float4*)&row[j0] = p;
            *(float4*)&probrow[j0] = p;
        }
    }

    // ----- Phase C: out = prob @ V_h (double-buffered V) -----
    STORE_CHUNK(0);
    __syncthreads();

    float oacc[4] = {0.f, 0.f, 0.f, 0.f};
    for (int c = 0; c < 4; c++) {
        if (c < 3) LOAD_CHUNK(g_v, c+1);
        const float* VtT = KB + (c & 1) * KTT_FLOATS;
        int jc = c * 128;
        #pragma unroll 8
        for (int jj = 0; jj < 128; jj += 4) {
            float4 v = *(const float4*)&VtT[lane*132 + jj];    // lane = d column
            #pragma unroll
            for (int i = 0; i < 4; i++) {
                float4 p = *(const float4*)&sc[(qg*4 + i)*512 + jc + jj];   // warp-broadcast
                oacc[i] += p.x*v.x + p.y*v.y + p.z*v.z + p.w*v.w;
            }
        }
        if (c < 3) {
            STORE_CHUNK((c+1) & 1);
            __syncthreads();
        }
    }
    #pragma unroll
    for (int i = 0; i < 4; i++)
        out[(size_t)(b*S_ + q0 + qg*4 + i) * D_ + h*DH_ + lane] = oacc[i];

    #undef LOAD_CHUNK
    #undef STORE_CHUNK
}

// ---------------------------------------------------------------------------
extern "C" void kernel_launch(void* const* d_in, const int* in_sizes, int n_in,
                              void* d_out, int out_size)
{
    const float* query = (const float*)d_in[0];
    const float* key_t = (const float*)d_in[1];
    const float* value = (const float*)d_in[2];
    const float* rel   = (const float*)d_in[3];
    const float* tsp   = (const float*)d_in[4];
    // d_in[5] = mask: deterministic triu(k=1), never read
    const float* l1p   = (const float*)d_in[6];
    const float* l2p   = (const float*)d_in[7];
    const float* Wq    = (const float*)d_in[8];
    const float* bq    = (const float*)d_in[9];
    const float* Wk    = (const float*)d_in[10];
    const float* bk    = (const float*)d_in[11];
    const float* Wv    = (const float*)d_in[12];
    const float* bv    = (const float*)d_in[13];

    float* out  = (float*)d_out;
    float* prob = out + (size_t)B_ * S_ * D_;

    cudaFuncSetAttribute(attn_kernel, cudaFuncAttributeMaxDynamicSharedMemorySize, ATTN_SMEM);

    proj_kernel<<<dim3(64, 2, 3), 256>>>(query, key_t, value, Wq, Wk, Wv, bq, bk, bv);
    tr_kernel<<<1024, 256>>>(rel, tsp, l1p, l2p);
    attn_kernel<<<dim3(16, 8, 16), 256, ATTN_SMEM>>>(l1p, l2p, out, prob);
}

// round 11
// speedup vs baseline: 1.6712x; 1.6712x over previous
#include <cuda_runtime.h>

#define B_ 16
#define S_ 512
#define D_ 256
#define H_ 8
#define DH_ 32

// Scratch (static device arrays — no allocations allowed)
__device__ float g_q[B_*S_*D_];
__device__ float g_k[B_*S_*D_];
__device__ float g_v[B_*S_*D_];
__device__ float g_tr[(size_t)B_*S_*S_];   // TR[b,q,j] = c2*time_attn + c3*rel_attn (head-independent)

__device__ __forceinline__ float ex2f_(float x){
    float y; asm("ex2.approx.ftz.f32 %0, %1;" : "=f"(y) : "f"(x)); return y;
}
__device__ __forceinline__ float fexp_(float x){ return ex2f_(x * 1.4426950408889634f); }

// ---------------------------------------------------------------------------
// Kernel 1: projections  P = X @ W^T + b  (M=8192, N=256, K=256)
// 128x64 block tile, 8x4 per-thread microtile (79 regs, no spill),
// double-buffered smem, register prefetch, one barrier per k-slab.
// launch_bounds(256,3): 79 < 85-reg cap -> 3 CTAs/SM.
// ---------------------------------------------------------------------------
__global__ void __launch_bounds__(256, 3) proj_kernel(
    const float* __restrict__ Xq, const float* __restrict__ Xk, const float* __restrict__ Xv,
    const float* __restrict__ Wq, const float* __restrict__ Wk, const float* __restrict__ Wv,
    const float* __restrict__ bq, const float* __restrict__ bk, const float* __restrict__ bv)
{
    __shared__ float As[2][16][132];   // [buf][k][m]
    __shared__ float Bs[2][16][68];    // [buf][k][n]

    int z = blockIdx.z;
    const float* X    = (z==0) ? Xq : ((z==1) ? Xk : Xv);
    const float* W    = (z==0) ? Wq : ((z==1) ? Wk : Wv);
    const float* bias = (z==0) ? bq : ((z==1) ? bk : bv);
    float*       O    = (z==0) ? g_q : ((z==1) ? g_k : g_v);

    int m0 = blockIdx.x * 128, n0 = blockIdx.y * 64;
    int tid = threadIdx.x;
    int tm = tid >> 4, tn = tid & 15;        // 16x16 threads; 8 rows x 4 cols each
    int lr = tid >> 2, lk = (tid & 3) * 4;   // loader: row lr (A also lr+64), k-offset lk

    const float* Arow0 = &X[(size_t)(m0 + lr)      * 256 + lk];
    const float* Arow1 = &X[(size_t)(m0 + lr + 64) * 256 + lk];
    const float* Brow  = &W[(size_t)(n0 + lr)      * 256 + lk];

    float acc[8][4];
    #pragma unroll
    for (int i = 0; i < 8; i++)
        #pragma unroll
        for (int j = 0; j < 4; j++) acc[i][j] = 0.f;

    // prefetch slab 0
    float4 na0 = *(const float4*)Arow0;
    float4 na1 = *(const float4*)Arow1;
    float4 nb  = *(const float4*)Brow;
    As[0][lk+0][lr] = na0.x; As[0][lk+1][lr] = na0.y; As[0][lk+2][lr] = na0.z; As[0][lk+3][lr] = na0.w;
    As[0][lk+0][lr+64] = na1.x; As[0][lk+1][lr+64] = na1.y; As[0][lk+2][lr+64] = na1.z; As[0][lk+3][lr+64] = na1.w;
    Bs[0][lk+0][lr] = nb.x; Bs[0][lk+1][lr] = nb.y; Bs[0][lk+2][lr] = nb.z; Bs[0][lk+3][lr] = nb.w;
    __syncthreads();

    int buf = 0;
    for (int step = 0; step < 16; step++) {
        if (step < 15) {
            int k0 = (step + 1) * 16;
            na0 = *(const float4*)(Arow0 + k0);
            na1 = *(const float4*)(Arow1 + k0);
            nb  = *(const float4*)(Brow  + k0);
        }
        #pragma unroll
        for (int kk = 0; kk < 16; kk++) {
            float4 a0 = *(const float4*)&As[buf][kk][tm*8];
            float4 a1 = *(const float4*)&As[buf][kk][tm*8 + 4];
            float4 bb = *(const float4*)&Bs[buf][kk][tn*4];
            acc[0][0] += a0.x*bb.x; acc[0][1] += a0.x*bb.y; acc[0][2] += a0.x*bb.z; acc[0][3] += a0.x*bb.w;
            acc[1][0] += a0.y*bb.x; acc[1][1] += a0.y*bb.y; acc[1][2] += a0.y*bb.z; acc[1][3] += a0.y*bb.w;
            acc[2][0] += a0.z*bb.x; acc[2][1] += a0.z*bb.y; acc[2][2] += a0.z*bb.z; acc[2][3] += a0.z*bb.w;
            acc[3][0] += a0.w*bb.x; acc[3][1] += a0.w*bb.y; acc[3][2] += a0.w*bb.z; acc[3][3] += a0.w*bb.w;
            acc[4][0] += a1.x*bb.x; acc[4][1] += a1.x*bb.y; acc[4][2] += a1.x*bb.z; acc[4][3] += a1.x*bb.w;
            acc[5][0] += a1.y*bb.x; acc[5][1] += a1.y*bb.y; acc[5][2] += a1.y*bb.z; acc[5][3] += a1.y*bb.w;
            acc[6][0] += a1.z*bb.x; acc[6][1] += a1.z*bb.y; acc[6][2] += a1.z*bb.z; acc[6][3] += a1.z*bb.w;
            acc[7][0] += a1.w*bb.x; acc[7][1] += a1.w*bb.y; acc[7][2] += a1.w*bb.z; acc[7][3] += a1.w*bb.w;
        }
        if (step < 15) {
            int nx = buf ^ 1;
            As[nx][lk+0][lr] = na0.x; As[nx][lk+1][lr] = na0.y; As[nx][lk+2][lr] = na0.z; As[nx][lk+3][lr] = na0.w;
            As[nx][lk+0][lr+64] = na1.x; As[nx][lk+1][lr+64] = na1.y; As[nx][lk+2][lr+64] = na1.z; As[nx][lk+3][lr+64] = na1.w;
            Bs[nx][lk+0][lr] = nb.x; Bs[nx][lk+1][lr] = nb.y; Bs[nx][lk+2][lr] = nb.z; Bs[nx][lk+3][lr] = nb.w;
            __syncthreads();
            buf = nx;
        }
    }

    float4 bv4 = *(const float4*)&bias[n0 + tn * 4];
    #pragma unroll
    for (int i = 0; i < 8; i++) {
        float4 o;
        o.x = acc[i][0] + bv4.x; o.y = acc[i][1] + bv4.y;
        o.z = acc[i][2] + bv4.z; o.w = acc[i][3] + bv4.w;
        *(float4*)&O[(size_t)(m0 + tm * 8 + i) * 256 + n0 + tn * 4] = o;
    }
}

// ---------------------------------------------------------------------------
// Kernel 2: TR precompute (head-independent blend of time/rel softmaxes)
// ---------------------------------------------------------------------------
__global__ void __launch_bounds__(256) tr_kernel(
    const float* __restrict__ rel, const float* __restrict__ ts,
    const float* __restrict__ l1p, const float* __restrict__ l2p)
{
    int w = blockIdx.x * 8 + (threadIdx.x >> 5);  // row (b*S + q)
    int lane = threadIdx.x & 31;
    int q = w & (S_ - 1);
    const float* relrow = rel + (size_t)w * S_;
    const float* tsrow  = ts  + (size_t)w * S_;

    float l1 = *l1p, l2 = *l2p;
    float c2 = (1.f - l1) * l2, c3 = l1;

    float tv[16], rv[16];
    float tsum = 0.f, rsum = 0.f;
    #pragma unroll
    for (int u = 0; u < 4; u++) {
        int j0 = lane * 4 + u * 128;
        float4 r4 = *(const float4*)&relrow[j0];
        float4 t4 = *(const float4*)&tsrow[j0];
        float rc[4] = {r4.x, r4.y, r4.z, r4.w};
        float tc[4] = {t4.x, t4.y, t4.z, t4.w};
        #pragma unroll
        for (int jj = 0; jj < 4; jj++) {
            int j = j0 + jj;
            float tnum = (j <= q) ? fexp_(fexp_(-fabsf(tc[jj]))) : 0.f;
            float rnum = (j > q && rc[jj] != 0.f) ? fexp_(rc[jj]) : 0.f;
            tv[4*u + jj] = tnum;  rv[4*u + jj] = rnum;
            tsum += tnum;  rsum += rnum;
        }
    }
    #pragma unroll
    for (int off = 16; off; off >>= 1) {
        tsum += __shfl_xor_sync(0xffffffffu, tsum, off);
        rsum += __shfl_xor_sync(0xffffffffu, rsum, off);
    }
    float tmul = c2 / tsum;
    float rmul = (rsum > 0.f) ? (c3 / rsum) : 0.f;
    float radd = (rsum > 0.f) ? 0.f : (c3 * (1.f / 512.f));

    float* trrow = g_tr + (size_t)w * S_;
    #pragma unroll
    for (int u = 0; u < 4; u++) {
        int j0 = lane * 4 + u * 128;
        float4 o;
        o.x = tv[4*u+0]*tmul + rv[4*u+0]*rmul + radd;
        o.y = tv[4*u+1]*tmul + rv[4*u+1]*rmul + radd;
        o.z = tv[4*u+2]*tmul + rv[4*u+2]*rmul + radd;
        o.w = tv[4*u+3]*tmul + rv[4*u+3]*rmul + radd;
        *(float4*)&trrow[j0] = o;
    }
}

// ---------------------------------------------------------------------------
// Kernel 3: fused attention. CTA = (q-tile of 32 rows, head, batch).
// Double-buffered K/V tiles; prefetch registers live ONLY across the GEMM
// compute (never across Phase B) to stay under the 128-reg 2-CTA cap.
// ---------------------------------------------------------------------------
#define SC_FLOATS   (32*512)
#define QST_FLOATS  (32*32)
#define KTT_FLOATS  (32*132)
#define ATTN_SMEM   ((SC_FLOATS + QST_FLOATS + 2*KTT_FLOATS) * 4)

__global__ void __launch_bounds__(256, 2) attn_kernel(
    const float* __restrict__ l1p, const float* __restrict__ l2p,
    float* __restrict__ out, float* __restrict__ prob)
{
    extern __shared__ float sm_[];
    float* sc  = sm_;                          // [32][512]
    float* QsT = sm_ + SC_FLOATS;              // [d=32][q=32]
    float* KB  = QsT + QST_FLOATS;             // two [32][132] buffers (K, then reused for V)

    int tid = threadIdx.x;
    int lane = tid & 31;
    int qg = tid >> 5;       // warp id: rows 4*qg .. 4*qg+3
    int kg = lane;
    int qt = blockIdx.x, h = blockIdx.y, b = blockIdx.z;
    int q0 = qt * 32;

    // loader mapping for K/V chunk (128 rows x 32 d): 4 float4 per thread
    int jr_[4], d0_[4];
    #pragma unroll
    for (int t = 0; t < 4; t++) { int id = tid + t*256; jr_[t] = id >> 3; d0_[t] = (id & 7) * 4; }

    float4 pr[4];
    #define LOAD_CHUNK(SRC, c) {                                                       \
        int jc = (c) * 128;                                                            \
        _Pragma("unroll")                                                              \
        for (int t = 0; t < 4; t++)                                                    \
            pr[t] = *(const float4*)&SRC[(size_t)(b*S_ + jc + jr_[t]) * D_ + h*DH_ + d0_[t]]; }
    #define STORE_CHUNK(bf) {                                                          \
        float* T = KB + (bf) * KTT_FLOATS;                                             \
        _Pragma("unroll")                                                              \
        for (int t = 0; t < 4; t++) {                                                  \
            T[(d0_[t]+0)*132 + jr_[t]] = pr[t].x;  T[(d0_[t]+1)*132 + jr_[t]] = pr[t].y; \
            T[(d0_[t]+2)*132 + jr_[t]] = pr[t].z;  T[(d0_[t]+3)*132 + jr_[t]] = pr[t].w; } }

    // Q tile load (transposed into d-major) + K chunk 0
    {
        int qr = tid >> 3, d0 = (tid & 7) * 4;
        float4 qv = *(const float4*)&g_q[(size_t)(b*S_ + q0 + qr) * D_ + h*DH_ + d0];
        LOAD_CHUNK(g_k, 0);
        QsT[(d0+0)*32 + qr] = qv.x; QsT[(d0+1)*32 + qr] = qv.y;
        QsT[(d0+2)*32 + qr] = qv.z; QsT[(d0+3)*32 + qr] = qv.w;
        STORE_CHUNK(0);
    }
    __syncthreads();

    const float SCALE = 0.25504570f;   // log2(e) / sqrt(32): softmax in base-2 domain
    float lmax[4] = {-1e30f, -1e30f, -1e30f, -1e30f};

    // ----- Phase A: scores (K double-buffered; prefetch hidden under compute) -----
    for (int c = 0; c < 4; c++) {
        if (c < 3) LOAD_CHUNK(g_k, c+1);
        const float* KtT = KB + (c & 1) * KTT_FLOATS;

        float acc[4][4];
        #pragma unroll
        for (int i = 0; i < 4; i++)
            #pragma unroll
            for (int j = 0; j < 4; j++) acc[i][j] = 0.f;

        #pragma unroll
        for (int d = 0; d < 32; d++) {
            float4 qv = *(const float4*)&QsT[d*32 + qg*4];     // warp-broadcast
            float4 kv = *(const float4*)&KtT[d*132 + kg*4];
            acc[0][0] += qv.x*kv.x; acc[0][1] += qv.x*kv.y; acc[0][2] += qv.x*kv.z; acc[0][3] += qv.x*kv.w;
            acc[1][0] += qv.y*kv.x; acc[1][1] += qv.y*kv.y; acc[1][2] += qv.y*kv.z; acc[1][3] += qv.y*kv.w;
            acc[2][0] += qv.z*kv.x; acc[2][1] += qv.z*kv.y; acc[2][2] += qv.z*kv.z; acc[2][3] += qv.z*kv.w;
            acc[3][0] += qv.w*kv.x; acc[3][1] += qv.w*kv.y; acc[3][2] += qv.w*kv.z; acc[3][3] += qv.w*kv.w;
        }
        int j0 = c*128 + kg*4;
        #pragma unroll
        for (int i = 0; i < 4; i++) {
            int qglob = q0 + qg*4 + i;
            float4 v;
            v.x = (j0+0 > qglob) ? -1e9f : acc[i][0]*SCALE;
            v.y = (j0+1 > qglob) ? -1e9f : acc[i][1]*SCALE;
            v.z = (j0+2 > qglob) ? -1e9f : acc[i][2]*SCALE;
            v.w = (j0+3 > qglob) ? -1e9f : acc[i][3]*SCALE;
            lmax[i] = fmaxf(lmax[i], fmaxf(fmaxf(v.x, v.y), fmaxf(v.z, v.w)));
            *(float4*)&sc[(qg*4 + i)*512 + j0] = v;
        }
        if (c < 3) {
            STORE_CHUNK((c+1) & 1);
            __syncthreads();
        }
    }
    #pragma unroll
    for (int off = 16; off; off >>= 1) {
        #pragma unroll
        for (int i = 0; i < 4; i++)
            lmax[i] = fmaxf(lmax[i], __shfl_xor_sync(0xffffffffu, lmax[i], off));
    }
    __syncwarp();

    // ----- Phase B: softmax + blend + prob write (no prefetch held across here) -----
    float l1 = *l1p, l2 = *l2p;
    float c1 = (1.f - l1) * (1.f - l2);

    #pragma unroll
    for (int i = 0; i < 4; i++) {
        int r = qg*4 + i;
        int qglob = q0 + r;
        float* row = &sc[r * 512];
        float e[16];
        float s = 0.f;
        float mx = lmax[i];
        #pragma unroll
        for (int u = 0; u < 4; u++) {
            float4 v = *(const float4*)&row[lane*4 + u*128];
            e[4*u+0] = ex2f_(v.x - mx);
            e[4*u+1] = ex2f_(v.y - mx);
            e[4*u+2] = ex2f_(v.z - mx);
            e[4*u+3] = ex2f_(v.w - mx);
            s += (e[4*u+0] + e[4*u+1]) + (e[4*u+2] + e[4*u+3]);
        }
        #pragma unroll
        for (int off = 16; off; off >>= 1) s += __shfl_xor_sync(0xffffffffu, s, off);
        float sA = c1 / s;

        const float* trrow = &g_tr[(size_t)(b*S_ + qglob) * S_];
        float* probrow = &prob[(size_t)((b*H_ + h)*S_ + qglob) * S_];
        #pragma unroll
        for (int u = 0; u < 4; u++) {
            int j0 = lane*4 + u*128;
            float4 t4 = *(const float4*)&trrow[j0];
            float4 p;
            p.x = e[4*u+0]*sA + t4.x;
            p.y = e[4*u+1]*sA + t4.y;
            p.z = e[4*u+2]*sA + t4.z;
            p.w = e[4*u+3]*sA + t4.w;
            *(float4*)&row[j0] = p;
            *(float4*)&probrow[j0] = p;
        }
    }

    // ----- Phase C: out = prob @ V_h (V double-buffered; chunk 0 exposed once) -----
    LOAD_CHUNK(g_v, 0);
    STORE_CHUNK(0);
    __syncthreads();

    float oacc[4] = {0.f, 0.f, 0.f, 0.f};
    for (int c = 0; c < 4; c++) {
        if (c < 3) LOAD_CHUNK(g_v, c+1);
        const float* VtT = KB + (c & 1) * KTT_FLOATS;
        int jc = c * 128;
        #pragma unroll 8
        for (int jj = 0; jj < 128; jj += 4) {
            float4 v = *(const float4*)&VtT[lane*132 + jj];    // lane = d column
            #pragma unroll
            for (int i = 0; i < 4; i++) {
                float4 p = *(const float4*)&sc[(qg*4 + i)*512 + jc + jj];   // warp-broadcast
                oacc[i] += p.x*v.x + p.y*v.y + p.z*v.z + p.w*v.w;
            }
        }
        if (c < 3) {
            STORE_CHUNK((c+1) & 1);
            __syncthreads();
        }
    }
    #pragma unroll
    for (int i = 0; i < 4; i++)
        out[(size_t)(b*S_ + q0 + qg*4 + i) * D_ + h*DH_ + lane] = oacc[i];

    #undef LOAD_CHUNK
    #undef STORE_CHUNK
}

// ---------------------------------------------------------------------------
extern "C" void kernel_launch(void* const* d_in, const int* in_sizes, int n_in,
                              void* d_out, int out_size)
{
    const float* query = (const float*)d_in[0];
    const float* key_t = (const float*)d_in[1];
    const float* value = (const float*)d_in[2];
    const float* rel   = (const float*)d_in[3];
    const float* tsp   = (const float*)d_in[4];
    // d_in[5] = mask: deterministic triu(k=1), never read
    const float* l1p   = (const float*)d_in[6];
    const float* l2p   = (const float*)d_in[7];
    const float* Wq    = (const float*)d_in[8];
    const float* bq    = (const float*)d_in[9];
    const float* Wk    = (const float*)d_in[10];
    const float* bk    = (const float*)d_in[11];
    const float* Wv    = (const float*)d_in[12];
    const float* bv    = (const float*)d_in[13];

    float* out  = (float*)d_out;
    float* prob = out + (size_t)B_ * S_ * D_;

    cudaFuncSetAttribute(attn_kernel, cudaFuncAttributeMaxDynamicSharedMemorySize, ATTN_SMEM);

    proj_kernel<<<dim3(64, 4, 3), 256>>>(query, key_t, value, Wq, Wk, Wv, bq, bk, bv);
    tr_kernel<<<1024, 256>>>(rel, tsp, l1p, l2p);
    attn_kernel<<<dim3(16, 8, 16), 256, ATTN_SMEM>>>(l1p, l2p, out, prob);
}